// round 1
// baseline (speedup 1.0000x reference)
#include <cuda_runtime.h>

#define G_   2048
#define NPG  128
#define NN   (G_*NPG)       // 262144 nodes
#define INC  151
#define HID  64
#define NE   2097152
#define NEG_SLOPE 0.2f

// ---------------- device scratch (allowed: __device__ globals) ----------------
__device__ float g_h[(size_t)NN * HID];   // 64 MB: transformed features
__device__ float g_as[NN];                // h . att_src
__device__ float g_ad[NN];                // h . att_dst
__device__ int   g_deg[NN];
__device__ int   g_fill[NN];
__device__ int   g_off[NN];
__device__ int   g_bsum[1024];
__device__ int   g_csr[NE];               // sources grouped by dst
__device__ float g_logits[G_];

// ---------------- K0: zero counters ----------------
__global__ void k_zero() {
    int i = blockIdx.x * blockDim.x + threadIdx.x;
    if (i < NN) { g_deg[i] = 0; g_fill[i] = 0; }
    if (i < G_) g_logits[i] = 0.f;
}

// ---------------- K1: h = x @ W1 (fp32 SIMT tiled GEMM) ----------------
// 64 rows per block, K chunked by 76 to stay under 48KB static smem.
#define KC 76
__global__ __launch_bounds__(256) void k_gemm(const float* __restrict__ x,
                                              const float* __restrict__ W) {
    __shared__ float sW[KC * 64];        // sW[k*64 + c]
    __shared__ float sX[KC * 68];        // sX[k*68 + r]  (pad 68: 16B aligned, low conflict)
    int tid  = threadIdx.x;
    int row0 = blockIdx.x * 64;
    int tx = tid & 15, ty = tid >> 4;    // 16 x 16 thread grid, 4x4 microtile

    float acc[4][4];
    #pragma unroll
    for (int i = 0; i < 4; i++)
        #pragma unroll
        for (int j = 0; j < 4; j++) acc[i][j] = 0.f;

    for (int c0 = 0; c0 < INC; c0 += KC) {
        int L = min(KC, INC - c0);
        // load W chunk: coalesced, conflict-free
        for (int i = tid; i < L * 64; i += 256) sW[i] = W[c0 * 64 + i];
        // load x chunk transposed: r-major enumeration -> coalesced gmem reads
        for (int i = tid; i < 64 * L; i += 256) {
            int r = i / L, k = i - r * L;
            sX[k * 68 + r] = x[(size_t)(row0 + r) * INC + (c0 + k)];
        }
        __syncthreads();
        #pragma unroll 2
        for (int k = 0; k < L; k++) {
            float4 a = *(const float4*)&sX[k * 68 + ty * 4];
            float4 b = *(const float4*)&sW[k * 64 + tx * 4];
            acc[0][0] = fmaf(a.x, b.x, acc[0][0]); acc[0][1] = fmaf(a.x, b.y, acc[0][1]);
            acc[0][2] = fmaf(a.x, b.z, acc[0][2]); acc[0][3] = fmaf(a.x, b.w, acc[0][3]);
            acc[1][0] = fmaf(a.y, b.x, acc[1][0]); acc[1][1] = fmaf(a.y, b.y, acc[1][1]);
            acc[1][2] = fmaf(a.y, b.z, acc[1][2]); acc[1][3] = fmaf(a.y, b.w, acc[1][3]);
            acc[2][0] = fmaf(a.z, b.x, acc[2][0]); acc[2][1] = fmaf(a.z, b.y, acc[2][1]);
            acc[2][2] = fmaf(a.z, b.z, acc[2][2]); acc[2][3] = fmaf(a.z, b.w, acc[2][3]);
            acc[3][0] = fmaf(a.w, b.x, acc[3][0]); acc[3][1] = fmaf(a.w, b.y, acc[3][1]);
            acc[3][2] = fmaf(a.w, b.z, acc[3][2]); acc[3][3] = fmaf(a.w, b.w, acc[3][3]);
        }
        __syncthreads();
    }
    #pragma unroll
    for (int ii = 0; ii < 4; ii++) {
        int row = row0 + ty * 4 + ii;
        float4 v = make_float4(acc[ii][0], acc[ii][1], acc[ii][2], acc[ii][3]);
        *(float4*)&g_h[(size_t)row * 64 + tx * 4] = v;
    }
}

// ---------------- K1b: per-node attention scores (warp per node) ----------------
__global__ void k_att(const float* __restrict__ att_src, const float* __restrict__ att_dst) {
    int gw   = (blockIdx.x * blockDim.x + threadIdx.x) >> 5;
    int lane = threadIdx.x & 31;
    if (gw >= NN) return;
    float2 h = *(const float2*)&g_h[(size_t)gw * 64 + lane * 2];
    float s0 = __ldg(&att_src[lane * 2]),     s1 = __ldg(&att_src[lane * 2 + 1]);
    float d0 = __ldg(&att_dst[lane * 2]),     d1 = __ldg(&att_dst[lane * 2 + 1]);
    float ps = h.x * s0 + h.y * s1;
    float pd = h.x * d0 + h.y * d1;
    #pragma unroll
    for (int o = 16; o; o >>= 1) {
        ps += __shfl_xor_sync(0xFFFFFFFFu, ps, o);
        pd += __shfl_xor_sync(0xFFFFFFFFu, pd, o);
    }
    if (lane == 0) { g_as[gw] = ps; g_ad[gw] = pd; }
}

// ---------------- K2: in-degree histogram ----------------
__global__ void k_hist(const int* __restrict__ ei) {
    int e = blockIdx.x * blockDim.x + threadIdx.x;
    if (e < NE) atomicAdd(&g_deg[ei[NE + e]], 1);
}

// ---------------- K3: 2-level exclusive scan over g_deg -> g_off ----------------
__global__ void k_scanA() {
    int t = threadIdx.x;
    int i = blockIdx.x * 256 + t;
    int v = g_deg[i];
    int lane = t & 31, w = t >> 5;
    int x = v;
    #pragma unroll
    for (int d = 1; d < 32; d <<= 1) { int y = __shfl_up_sync(0xFFFFFFFFu, x, d); if (lane >= d) x += y; }
    __shared__ int wt[8];
    if (lane == 31) wt[w] = x;
    __syncthreads();
    if (t < 8) {
        int s = wt[t];
        int xs = s;
        #pragma unroll
        for (int d = 1; d < 8; d <<= 1) { int y = __shfl_up_sync(0xFFu, xs, d); if (t >= d) xs += y; }
        wt[t] = xs - s;   // exclusive warp-total prefix
    }
    __syncthreads();
    int incl = x + wt[w];
    g_off[i] = incl - v;
    if (t == 255) g_bsum[blockIdx.x] = incl;
}

__global__ void k_scanB() {
    int t = threadIdx.x;           // 1024 threads
    int lane = t & 31, w = t >> 5;
    int v = g_bsum[t];
    int x = v;
    #pragma unroll
    for (int d = 1; d < 32; d <<= 1) { int y = __shfl_up_sync(0xFFFFFFFFu, x, d); if (lane >= d) x += y; }
    __shared__ int wt[32];
    if (lane == 31) wt[w] = x;
    __syncthreads();
    if (w == 0) {
        int s = wt[lane];
        int xs = s;
        #pragma unroll
        for (int d = 1; d < 32; d <<= 1) { int y = __shfl_up_sync(0xFFFFFFFFu, xs, d); if (lane >= d) xs += y; }
        wt[lane] = xs - s;
    }
    __syncthreads();
    g_bsum[t] = x - v + wt[w];     // exclusive
}

__global__ void k_scanC() {
    int i = blockIdx.x * 256 + threadIdx.x;
    g_off[i] += g_bsum[i >> 8];
}

// ---------------- K4: scatter sources into CSR grouped by dst ----------------
__global__ void k_scatter(const int* __restrict__ ei) {
    int e = blockIdx.x * blockDim.x + threadIdx.x;
    if (e >= NE) return;
    int dst = ei[NE + e];
    int src = ei[e];
    int p = g_off[dst] + atomicAdd(&g_fill[dst], 1);
    g_csr[p] = src;
}

// ---------------- K5: per-node softmax aggregation + ReLU + graph-linear ----------------
__global__ __launch_bounds__(256) void k_agg(const float* __restrict__ b1,
                                             const float* __restrict__ Wlin) {
    __shared__ float s_ex[8][64];
    int lane = threadIdx.x & 31;
    int wid  = threadIdx.x >> 5;
    int node = blockIdx.x * 8 + wid;

    float ad_i = g_ad[node];
    float a0 = g_as[node] + ad_i;
    a0 = a0 >= 0.f ? a0 : NEG_SLOPE * a0;                 // self-loop score
    int deg   = g_deg[node];
    int start = g_off[node];

    // pass 1: max (cache raw alphas for deg<=64, which is effectively always)
    float m = a0;
    for (int e = lane; e < deg; e += 32) {
        int s = g_csr[start + e];
        float a = g_as[s] + ad_i;
        a = a >= 0.f ? a : NEG_SLOPE * a;
        if (e < 64) s_ex[wid][e] = a;
        m = fmaxf(m, a);
    }
    #pragma unroll
    for (int o = 16; o; o >>= 1) m = fmaxf(m, __shfl_xor_sync(0xFFFFFFFFu, m, o));
    __syncwarp();

    // pass 2: sum of exp
    float z = (lane == 0) ? __expf(a0 - m) : 0.f;
    for (int e = lane; e < deg; e += 32) {
        float a;
        if (e < 64) a = s_ex[wid][e];
        else { int s = g_csr[start + e]; a = g_as[s] + ad_i; a = a >= 0.f ? a : NEG_SLOPE * a; }
        float ex = __expf(a - m);
        if (e < 64) s_ex[wid][e] = ex;
        z += ex;
    }
    #pragma unroll
    for (int o = 16; o; o >>= 1) z += __shfl_xor_sync(0xFFFFFFFFu, z, o);
    float invz = 1.f / z;
    __syncwarp();

    // pass 3: channel-parallel gather-accumulate (2 channels per lane)
    float w0 = __expf(a0 - m) * invz;
    float2 hi = *(const float2*)&g_h[(size_t)node * 64 + lane * 2];
    float accx = w0 * hi.x, accy = w0 * hi.y;
    for (int e = 0; e < deg; e++) {
        int s = g_csr[start + e];
        float w;
        if (e < 64) w = s_ex[wid][e] * invz;
        else {
            float a = g_as[s] + ad_i; a = a >= 0.f ? a : NEG_SLOPE * a;
            w = __expf(a - m) * invz;
        }
        float2 hs = *(const float2*)&g_h[(size_t)s * 64 + lane * 2];
        accx = fmaf(w, hs.x, accx);
        accy = fmaf(w, hs.y, accy);
    }

    // bias + ReLU + per-graph linear partial
    float2 bb = *(const float2*)&b1[lane * 2];
    float rx = fmaxf(accx + bb.x, 0.f);
    float ry = fmaxf(accy + bb.y, 0.f);
    int local = node & (NPG - 1);
    float2 wl = *(const float2*)&Wlin[local * 64 + lane * 2];
    float p = rx * wl.x + ry * wl.y;
    #pragma unroll
    for (int o = 16; o; o >>= 1) p += __shfl_xor_sync(0xFFFFFFFFu, p, o);
    if (lane == 0) atomicAdd(&g_logits[node >> 7], p);
}

// ---------------- K6: bias + sigmoid ----------------
__global__ void k_fin(const float* __restrict__ blin, float* __restrict__ out) {
    int i = blockIdx.x * blockDim.x + threadIdx.x;
    if (i < G_) {
        float l = g_logits[i] + blin[0];
        out[i] = 1.f / (1.f + __expf(-l));
    }
}

// ---------------- launch ----------------
extern "C" void kernel_launch(void* const* d_in, const int* in_sizes, int n_in,
                              void* d_out, int out_size) {
    const float* x    = (const float*)d_in[0];
    const int*   ei   = (const int*)  d_in[1];
    const float* W1   = (const float*)d_in[2];
    const float* asv  = (const float*)d_in[3];
    const float* adv  = (const float*)d_in[4];
    const float* b1   = (const float*)d_in[5];
    const float* Wlin = (const float*)d_in[6];
    const float* blin = (const float*)d_in[7];
    float* out = (float*)d_out;

    k_zero   <<<NN / 256, 256>>>();
    k_gemm   <<<NN / 64, 256>>>(x, W1);
    k_att    <<<NN / 8, 256>>>(asv, adv);
    k_hist   <<<NE / 256, 256>>>(ei);
    k_scanA  <<<1024, 256>>>();
    k_scanB  <<<1, 1024>>>();
    k_scanC  <<<1024, 256>>>();
    k_scatter<<<NE / 256, 256>>>(ei);
    k_agg    <<<NN / 8, 256>>>(b1, Wlin);
    k_fin    <<<G_ / 256, 256>>>(blin, out);
}